// round 15
// baseline (speedup 1.0000x reference)
#include <cuda_runtime.h>
#include <cuda_bf16.h>
#include <cstdint>

#define B_ 4
#define S_ 2048
#define D_ 1024
#define H_ 16
#define DH_ 64
#define MROWS (B_ * S_)
#define QKV_ELEMS (B_ * H_ * S_ * DH_)   // 8388608
#define C_ELEMS   (B_ * S_ * D_)         // 8388608

// -------- bf16 hi/lo scratch (no allocation) --------
__device__ __nv_bfloat16 g_xh[C_ELEMS],  g_xl[C_ELEMS];
__device__ __nv_bfloat16 g_wt_h[3 * H_ * DH_ * D_], g_wt_l[3 * H_ * DH_ * D_];
__device__ __nv_bfloat16 g_wo_h[D_ * D_], g_wo_l[D_ * D_];
__device__ __nv_bfloat16 g_qh[QKV_ELEMS], g_ql[QKV_ELEMS];
__device__ __nv_bfloat16 g_kh[QKV_ELEMS], g_kl[QKV_ELEMS];
__device__ __nv_bfloat16 g_vh[QKV_ELEMS], g_vl[QKV_ELEMS];
__device__ __nv_bfloat16 g_ch[C_ELEMS],  g_cl[C_ELEMS];

// work-steal counters: [0]=qkv, [1]=attn, [2]=out_proj
__device__ unsigned int g_ctrs[3];

#define PERSIST_CTAS 304

// ================= helpers =================
__device__ __forceinline__ uint32_t smem_u32(const void* p) {
    uint32_t a;
    asm("{ .reg .u64 t; cvta.to.shared.u64 t, %1; cvt.u32.u64 %0, t; }" : "=r"(a) : "l"(p));
    return a;
}
__device__ __forceinline__ void bsplit(float v, float& h, float& l) {
    __nv_bfloat16 bh = __float2bfloat16(v);
    h = __bfloat162float(bh);
    l = v - h;
}
__device__ __forceinline__ uint32_t packbf(float lo_elem, float hi_elem) {
    uint32_t r;
    asm("cvt.rn.bf16x2.f32 %0, %1, %2;" : "=r"(r) : "f"(hi_elem), "f"(lo_elem));
    return r;
}
#define LDSM_X4(r0, r1, r2, r3, addr) \
    asm volatile("ldmatrix.sync.aligned.m8n8.x4.shared.b16 {%0,%1,%2,%3}, [%4];" \
        : "=r"(r0), "=r"(r1), "=r"(r2), "=r"(r3) : "r"(addr))
#define LDSM_X4_T(r0, r1, r2, r3, addr) \
    asm volatile("ldmatrix.sync.aligned.m8n8.x4.trans.shared.b16 {%0,%1,%2,%3}, [%4];" \
        : "=r"(r0), "=r"(r1), "=r"(r2), "=r"(r3) : "r"(addr))
#define CP_A16(sa, gp) asm volatile("cp.async.ca.shared.global [%0], [%1], 16;" :: "r"(sa), "l"(gp))
#define CP_COMMIT()    asm volatile("cp.async.commit_group;" ::: "memory")
#define CP_WAIT(n)     asm volatile("cp.async.wait_group %0;" :: "n"(n) : "memory")

__device__ __forceinline__ void mma16816(float* c,
    uint32_t a0, uint32_t a1, uint32_t a2, uint32_t a3, uint32_t b0, uint32_t b1)
{
    asm volatile(
        "mma.sync.aligned.m16n8k16.row.col.f32.bf16.bf16.f32 "
        "{%0,%1,%2,%3}, {%4,%5,%6,%7}, {%8,%9}, {%0,%1,%2,%3};"
        : "+f"(c[0]), "+f"(c[1]), "+f"(c[2]), "+f"(c[3])
        : "r"(a0), "r"(a1), "r"(a2), "r"(a3), "r"(b0), "r"(b1));
}

// ============================================================
// Fused preconversion kernel (x + W + Wo, one launch).
// ============================================================
__global__ __launch_bounds__(256) void conv_all_kernel(
    const float* __restrict__ x,
    const float* __restrict__ Wq, const float* __restrict__ Wk,
    const float* __restrict__ Wv, const float* __restrict__ Wo)
{
    __shared__ float ts[64][65];
    const int blk = blockIdx.x;
    const int tid = threadIdx.x;

    if (blk < 8192) {
        if (blk == 0 && tid < 3) g_ctrs[tid] = 0u;
        int i = blk * 256 + tid;
        float4 v = *(const float4*)(x + 4 * (size_t)i);
        float hx, lx, hy, ly, hz, lz, hw, lw;
        bsplit(v.x, hx, lx); bsplit(v.y, hy, ly);
        bsplit(v.z, hz, lz); bsplit(v.w, hw, lw);
        uint2 wh, wl;
        wh.x = packbf(hx, hy); wh.y = packbf(hz, hw);
        wl.x = packbf(lx, ly); wl.y = packbf(lz, lw);
        *(uint2*)(g_xh + 4 * (size_t)i) = wh;
        *(uint2*)(g_xl + 4 * (size_t)i) = wl;
        return;
    }

    if (blk < 8960) {
        const int q = blk - 8192;
        const int d0 = (q & 15) * 64;
        const int h  = (q >> 4) & 15;
        const int z  = q >> 8;
        const float* W = (z == 0) ? Wq : ((z == 1) ? Wk : Wv);
        const float* src = W + (size_t)h * D_ * DH_;

        #pragma unroll
        for (int i = 0; i < 4; ++i) {
            int idx = tid + i * 256;
            int rr = idx >> 4, cc = idx & 15;
            float4 v = *(const float4*)(src + (size_t)(d0 + rr) * DH_ + cc * 4);
            ts[rr][cc * 4 + 0] = v.x; ts[rr][cc * 4 + 1] = v.y;
            ts[rr][cc * 4 + 2] = v.z; ts[rr][cc * 4 + 3] = v.w;
        }
        __syncthreads();
        #pragma unroll
        for (int i = 0; i < 8; ++i) {
            int idx = tid + i * 256;
            int e = idx >> 5, w = idx & 31;
            float v0 = ts[2 * w][e], v1 = ts[2 * w + 1][e];
            float h0, l0, h1, l1;
            bsplit(v0, h0, l0); bsplit(v1, h1, l1);
            size_t off = ((size_t)(z * H_ + h) * DH_ + e) * D_ + d0 + 2 * w;
            *(uint32_t*)(g_wt_h + off) = packbf(h0, h1);
            *(uint32_t*)(g_wt_l + off) = packbf(l0, l1);
        }
        return;
    }

    {
        const int q = blk - 8960;
        const int d0 = (q & 15) * 64;
        const int f0 = (q >> 4) * 64;

        #pragma unroll
        for (int i = 0; i < 4; ++i) {
            int idx = tid + i * 256;
            int rr = idx >> 4, cc = idx & 15;
            float4 v = *(const float4*)(Wo + (size_t)(d0 + rr) * D_ + f0 + cc * 4);
            ts[rr][cc * 4 + 0] = v.x; ts[rr][cc * 4 + 1] = v.y;
            ts[rr][cc * 4 + 2] = v.z; ts[rr][cc * 4 + 3] = v.w;
        }
        __syncthreads();
        #pragma unroll
        for (int i = 0; i < 8; ++i) {
            int idx = tid + i * 256;
            int e = idx >> 5, w = idx & 31;
            float v0 = ts[2 * w][e], v1 = ts[2 * w + 1][e];
            float h0, l0, h1, l1;
            bsplit(v0, h0, l0); bsplit(v1, h1, l1);
            size_t off = (size_t)(f0 + e) * D_ + d0 + 2 * w;
            *(uint32_t*)(g_wo_h + off) = packbf(h0, h1);
            *(uint32_t*)(g_wo_l + off) = packbf(l0, l1);
        }
    }
}

// ============================================================
// GEMM machinery (R13 proven): 128x128 tile, BK=32, 8 warps,
// 2-stage cp.async, 2 CTAs/SM, persistent, ONE barrier/ktile,
// R12-style LDSM/MMA interleave.
// ============================================================
#define GEMM_STAGE 40960
#define GEMM_SMEM (2 * GEMM_STAGE)
#define NKT (D_ / 32)

__device__ __forceinline__ void gemm_load_stage(uint32_t sbase,
    const __nv_bfloat16* p0, const __nv_bfloat16* p1,
    const __nv_bfloat16* p2, const __nv_bfloat16* p3, int tid)
{
    const __nv_bfloat16* p[4] = {p0, p1, p2, p3};
    #pragma unroll
    for (int i = 0; i < 8; ++i) {
        int idx = tid + i * 256;
        int arr = idx >> 9;
        int c = idx & 511;
        int r = c >> 2, col = c & 3;
        const __nv_bfloat16* src = p[arr] + (size_t)r * D_ + col * 8;
        uint32_t sa = sbase + arr * 10240 + r * 80 + col * 16;
        CP_A16(sa, src);
    }
}

__device__ __forceinline__ void mma_phase(uint32_t sbase, float acc[4][4][4], int wid, int lane)
{
    const int warp_m = wid & 1;
    const int warp_n = wid >> 1;
    const uint32_t a_hi_b = sbase;
    const uint32_t a_lo_b = sbase + 10240;
    const uint32_t b_hi_b = sbase + 20480;
    const uint32_t b_lo_b = sbase + 30720;

    const int a_row = warp_m * 64 + (lane & 15);
    const int a_kh  = (lane >> 4) << 3;
    const int b_row = warp_n * 32 + (lane & 7) + ((lane >> 4) << 3);
    const int b_kh  = ((lane >> 3) & 1) << 3;

    #pragma unroll
    for (int ks = 0; ks < 2; ++ks) {
        const int koff = ks * 16;
        uint32_t bh[2][4], bl[2][4];
        #pragma unroll
        for (int jj = 0; jj < 2; ++jj) {
            LDSM_X4(bh[jj][0], bh[jj][1], bh[jj][2], bh[jj][3],
                    b_hi_b + ((b_row + jj * 16) * 40 + koff + b_kh) * 2);
            LDSM_X4(bl[jj][0], bl[jj][1], bl[jj][2], bl[jj][3],
                    b_lo_b + ((b_row + jj * 16) * 40 + koff + b_kh) * 2);
        }
        #pragma unroll
        for (int i = 0; i < 4; ++i) {
            uint32_t a0, a1, a2, a3;
            LDSM_X4(a0, a1, a2, a3,
                    a_hi_b + ((a_row + i * 16) * 40 + koff + a_kh) * 2);
            #pragma unroll
            for (int j = 0; j < 4; ++j) {
                int jj = j >> 1, s = (j & 1) * 2;
                mma16816(acc[i][j], a0, a1, a2, a3, bh[jj][s], bh[jj][s + 1]);
                mma16816(acc[i][j], a0, a1, a2, a3, bl[jj][s], bl[jj][s + 1]);
            }
            LDSM_X4(a0, a1, a2, a3,
                    a_lo_b + ((a_row + i * 16) * 40 + koff + a_kh) * 2);
            #pragma unroll
            for (int j = 0; j < 4; ++j) {
                int jj = j >> 1, s = (j & 1) * 2;
                mma16816(acc[i][j], a0, a1, a2, a3, bh[jj][s], bh[jj][s + 1]);
            }
        }
    }
}

#define GEMM_MAINLOOP(AH_, AL_, BH_, BL_)                                      \
    gemm_load_stage(smb, (AH_), (AL_), (BH_), (BL_), tid);                     \
    CP_COMMIT();                                                               \
    for (int kt = 0; kt < NKT; ++kt) {                                         \
        CP_WAIT(0);                                                            \
        __syncthreads();                                                       \
        if (kt + 1 < NKT) {                                                    \
            int k1 = (kt + 1) * 32;                                            \
            gemm_load_stage(smb + ((kt + 1) & 1) * GEMM_STAGE,                 \
                            (AH_) + k1, (AL_) + k1, (BH_) + k1, (BL_) + k1, tid); \
            CP_COMMIT();                                                       \
        }                                                                      \
        mma_phase(smb + (kt & 1) * GEMM_STAGE, acc, wid, lane);                \
    }

// ============================================================
// Kernel 1: QKV projection, persistent. tiles = 64*8*3 = 1536.
// ============================================================
#define QKV_TILES 1536

__global__ __launch_bounds__(256, 2) void qkv_mma_kernel()
{
    extern __shared__ char sm[];
    __shared__ int s_idx;
    const uint32_t smb = smem_u32(sm);
    const int tid = threadIdx.x;
    const int wid = tid >> 5;
    const int lane = tid & 31;

    for (;;) {
        if (tid == 0) s_idx = (int)atomicAdd(&g_ctrs[0], 1u);
        __syncthreads();
        const int idx = s_idx;
        if (idx >= QKV_TILES) return;

        const int m0 = (idx & 63) * 128;
        const int hp = (idx >> 6) & 7;
        const int z  = idx >> 9;

        __nv_bfloat16* outh = (z == 0) ? g_qh : ((z == 1) ? g_kh : g_vh);
        __nv_bfloat16* outl = (z == 0) ? g_ql : ((z == 1) ? g_kl : g_vl);
        const float scale = (z == 0) ? 0.125f : 1.0f;

        const __nv_bfloat16* ah = g_xh + (size_t)m0 * D_;
        const __nv_bfloat16* al = g_xl + (size_t)m0 * D_;
        const __nv_bfloat16* bh = g_wt_h + (size_t)(z * H_ + hp * 2) * DH_ * D_;
        const __nv_bfloat16* bl = g_wt_l + (size_t)(z * H_ + hp * 2) * DH_ * D_;

        float acc[4][4][4];
        #pragma unroll
        for (int i = 0; i < 4; ++i)
            #pragma unroll
            for (int j = 0; j < 4; ++j)
                #pragma unroll
                for (int q = 0; q < 4; ++q) acc[i][j][q] = 0.f;

        GEMM_MAINLOOP(ah, al, bh, bl)

        const int warp_m = wid & 1;
        const int warp_n = wid >> 1;
        #pragma unroll
        for (int i = 0; i < 4; ++i) {
            #pragma unroll
            for (int j = 0; j < 4; ++j) {
                int r0 = m0 + warp_m * 64 + i * 16 + (lane >> 2);
                int col = warp_n * 32 + j * 8 + (lane & 3) * 2;
                int hh = hp * 2 + (col >> 6);
                int ee = col & 63;
                #pragma unroll
                for (int half = 0; half < 2; ++half) {
                    int r = r0 + half * 8;
                    int b = r >> 11, s = r & 2047;
                    float v0 = acc[i][j][2 * half] * scale;
                    float v1 = acc[i][j][2 * half + 1] * scale;
                    float h0, l0, h1, l1;
                    bsplit(v0, h0, l0); bsplit(v1, h1, l1);
                    size_t off = ((size_t)(b * H_ + hh) * S_ + s) * DH_ + ee;
                    *(uint32_t*)(outh + off) = packbf(h0, h1);
                    *(uint32_t*)(outl + off) = packbf(l0, l1);
                }
            }
        }
        __syncthreads();
    }
}

// ============================================================
// Kernel 3: output projection, persistent. tiles = 64*8 = 512.
// ============================================================
#define OUT_TILES 512

__global__ __launch_bounds__(256, 2) void out_proj_mma_kernel(
    const float* __restrict__ bo, float* __restrict__ out)
{
    extern __shared__ char sm[];
    __shared__ int s_idx;
    const uint32_t smb = smem_u32(sm);
    const int tid = threadIdx.x;
    const int wid = tid >> 5;
    const int lane = tid & 31;

    for (;;) {
        if (tid == 0) s_idx = (int)atomicAdd(&g_ctrs[2], 1u);
        __syncthreads();
        const int idx = s_idx;
        if (idx >= OUT_TILES) return;

        const int m0 = (idx & 63) * 128;
        const int n0 = (idx >> 6) * 128;

        const __nv_bfloat16* ah = g_ch + (size_t)m0 * D_;
        const __nv_bfloat16* al = g_cl + (size_t)m0 * D_;
        const __nv_bfloat16* bh = g_wo_h + (size_t)n0 * D_;
        const __nv_bfloat16* bl = g_wo_l + (size_t)n0 * D_;

        float acc[4][4][4];
        #pragma unroll
        for (int i = 0; i < 4; ++i)
            #pragma unroll
            for (int j = 0; j < 4; ++j)
                #pragma unroll
                for (int q = 0; q < 4; ++q) acc[i][j][q] = 0.f;

        GEMM_MAINLOOP(ah, al, bh, bl)

        const int warp_m = wid & 1;
        const int warp_n = wid >> 1;
        #pragma unroll
        for (int i = 0; i < 4; ++i) {
            #pragma unroll
            for (int j = 0; j < 4; ++j) {
                int r0 = m0 + warp_m * 64 + i * 16 + (lane >> 2);
                int col = n0 + warp_n * 32 + j * 8 + (lane & 3) * 2;
                float b0 = bo[col], b1 = bo[col + 1];
                {
                    float2 v; v.x = acc[i][j][0] + b0; v.y = acc[i][j][1] + b1;
                    *(float2*)(out + (size_t)r0 * D_ + col) = v;
                }
                {
                    float2 v; v.x = acc[i][j][2] + b0; v.y = acc[i][j][3] + b1;
                    *(float2*)(out + (size_t)(r0 + 8) * D_ + col) = v;
                }
            }
        }
        __syncthreads();
    }
}

// ============================================================
// Kernel 2: causal flash attention, persistent + LPT,
// NEW: fully-masked warp-groups skipped in diagonal tiles (QK and PV).
// ============================================================
#define KV_STAGE 36864
#define ATTN_SMEM (36864 + 2 * KV_STAGE)
#define ATTN_TILES 1024

__device__ __forceinline__ void attn_load_kv(uint32_t kvb,
    const __nv_bfloat16* kh, const __nv_bfloat16* kl,
    const __nv_bfloat16* vh, const __nv_bfloat16* vl, int tid)
{
    const __nv_bfloat16* p[4] = {kh, kl, vh, vl};
    #pragma unroll
    for (int i = 0; i < 8; ++i) {
        int idx = tid + i * 256;
        int arr = idx >> 9;
        int c = idx & 511;
        int r = c >> 3, c8 = c & 7;
        const __nv_bfloat16* src = p[arr] + (size_t)r * DH_ + c8 * 8;
        uint32_t sa = kvb + arr * 9216 + r * 144 + c8 * 16;
        CP_A16(sa, src);
    }
}

__global__ __launch_bounds__(256, 2) void attn_mma_kernel()
{
    extern __shared__ char sm[];
    __shared__ int s_idx;
    const uint32_t smb = smem_u32(sm);
    const int tid = threadIdx.x;
    const int wm = tid >> 5;
    const int lane = tid & 31;

    const uint32_t Qh_b = smb;
    const uint32_t Ql_b = smb + 18432;

    for (;;) {
        if (tid == 0) s_idx = (int)atomicAdd(&g_ctrs[1], 1u);
        __syncthreads();
        const int idx = s_idx;
        if (idx >= ATTN_TILES) return;

        const int qb = 15 - (idx >> 6);
        const int bh = idx & 63;
        const int kmax = 2 * qb + 2;

        const __nv_bfloat16* kh_g = g_kh + (size_t)bh * S_ * DH_;
        const __nv_bfloat16* kl_g = g_kl + (size_t)bh * S_ * DH_;
        const __nv_bfloat16* vh_g = g_vh + (size_t)bh * S_ * DH_;
        const __nv_bfloat16* vl_g = g_vl + (size_t)bh * S_ * DH_;

        attn_load_kv(smb + 36864, kh_g, kl_g, vh_g, vl_g, tid);
        CP_COMMIT();

        {
            const __nv_bfloat16* qh_g = g_qh + ((size_t)bh * S_ + qb * 128) * DH_;
            const __nv_bfloat16* ql_g = g_ql + ((size_t)bh * S_ + qb * 128) * DH_;
            #pragma unroll
            for (int i = 0; i < 4; ++i) {
                int ii = tid + i * 256;
                int r = ii >> 3, c8 = ii & 7;
                *(uint4*)(sm + (Qh_b - smb) + r * 144 + c8 * 16) =
                    *(const uint4*)(qh_g + (size_t)r * DH_ + c8 * 8);
                *(uint4*)(sm + (Ql_b - smb) + r * 144 + c8 * 16) =
                    *(const uint4*)(ql_g + (size_t)r * DH_ + c8 * 8);
            }
        }
        __syncthreads();

        uint32_t qh[4][4], ql[4][4];
        {
            const int ar = wm * 16 + (lane & 15);
            const int koff = (lane >> 4) << 3;
            #pragma unroll
            for (int ks = 0; ks < 4; ++ks) {
                LDSM_X4(qh[ks][0], qh[ks][1], qh[ks][2], qh[ks][3],
                        Qh_b + ar * 144 + (ks * 16 + koff) * 2);
                LDSM_X4(ql[ks][0], ql[ks][1], ql[ks][2], ql[ks][3],
                        Ql_b + ar * 144 + (ks * 16 + koff) * 2);
            }
        }

        float mA = -3.0e38f, mB = -3.0e38f, lA = 0.f, lB = 0.f;
        float oacc[8][4];
        #pragma unroll
        for (int t = 0; t < 8; ++t)
            #pragma unroll
            for (int q = 0; q < 4; ++q) oacc[t][q] = 0.f;

        const int kb_row  = (lane & 7) + ((lane >> 4) << 3);
        const int kb_koff = ((lane >> 3) & 1) << 3;
        const int vb_row  = (lane & 7) + (((lane >> 3) & 1) << 3);
        const int vb_eoff = (lane >> 4) << 3;

        const int rA_g = qb * 128 + wm * 16 + (lane >> 2);

        for (int kt = 0; kt < kmax; ++kt) {
            CP_WAIT(0);
            __syncthreads();
            if (kt + 1 < kmax) {
                size_t koff = (size_t)(kt + 1) * 64 * DH_;
                attn_load_kv(smb + 36864 + ((kt + 1) & 1) * KV_STAGE,
                             kh_g + koff, kl_g + koff, vh_g + koff, vl_g + koff, tid);
                CP_COMMIT();
            }

            const uint32_t kvb = smb + 36864 + (kt & 1) * KV_STAGE;
            const uint32_t Kh_b = kvb, Kl_b = kvb + 9216, Vh_b = kvb + 18432, Vl_b = kvb + 27648;

            // diagonal-tile skip limit: group g fully masked iff g > skip_lim
            const int diag = kt - 2 * qb;                 // >=0 on diagonal pair
            const int skip_lim = (diag < 0) ? 3 : (wm - 4 * diag);

            float sacc[8][4];
            #pragma unroll
            for (int t = 0; t < 8; ++t)
                #pragma unroll
                for (int q = 0; q < 4; ++q) sacc[t][q] = 0.f;

            #pragma unroll
            for (int ks = 0; ks < 4; ++ks) {
                #pragma unroll
                for (int np = 0; np < 4; ++np) {
                    if (np > skip_lim) continue;   // fully-masked group
                    uint32_t row = np * 16 + kb_row;
                    uint32_t ko  = ks * 16 + kb_koff;
                    uint32_t b0, b1, b2, b3, c0, c1, c2, c3;
                    LDSM_X4(b0, b1, b2, b3, Kh_b + row * 144 + ko * 2);
                    LDSM_X4(c0, c1, c2, c3, Kl_b + row * 144 + ko * 2);
                    mma16816(sacc[2 * np],     qh[ks][0], qh[ks][1], qh[ks][2], qh[ks][3], b0, b1);
                    mma16816(sacc[2 * np],     qh[ks][0], qh[ks][1], qh[ks][2], qh[ks][3], c0, c1);
                    mma16816(sacc[2 * np],     ql[ks][0], ql[ks][1], ql[ks][2], ql[ks][3], b0, b1);
                    mma16816(sacc[2 * np + 1], qh[ks][0], qh[ks][1], qh[ks][2], qh[ks][3], b2, b3);
                    mma16816(sacc[2 * np + 1], qh[ks][0], qh[ks][1], qh[ks][2], qh[ks][3], c2, c3);
                    mma16816(sacc[2 * np + 1], ql[ks][0], ql[ks][1], ql[ks][2], ql[ks][3], b2, b3);
                }
            }

            if (diag >= 0) {
                const int c0g = kt * 64 + 2 * (lane & 3);
                #pragma unroll
                for (int t = 0; t < 8; ++t) {
                    int c = c0g + 8 * t;
                    if (c     > rA_g)     sacc[t][0] = -3.0e38f;
                    if (c + 1 > rA_g)     sacc[t][1] = -3.0e38f;
                    if (c     > rA_g + 8) sacc[t][2] = -3.0e38f;
                    if (c + 1 > rA_g + 8) sacc[t][3] = -3.0e38f;
                }
            }

            float mtA = -3.0e38f, mtB = -3.0e38f;
            #pragma unroll
            for (int t = 0; t < 8; ++t) {
                mtA = fmaxf(mtA, fmaxf(sacc[t][0], sacc[t][1]));
                mtB = fmaxf(mtB, fmaxf(sacc[t][2], sacc[t][3]));
            }
            mtA = fmaxf(mtA, __shfl_xor_sync(0xffffffffu, mtA, 1));
            mtA = fmaxf(mtA, __shfl_xor_sync(0xffffffffu, mtA, 2));
            mtB = fmaxf(mtB, __shfl_xor_sync(0xffffffffu, mtB, 1));
            mtB = fmaxf(mtB, __shfl_xor_sync(0xffffffffu, mtB, 2));

            float mnA = fmaxf(mA, mtA), mnB = fmaxf(mB, mtB);
            float corrA = __expf(mA - mnA), corrB = __expf(mB - mnB);

            float rsA = 0.f, rsB = 0.f;
            #pragma unroll
            for (int t = 0; t < 8; ++t) {
                float p0 = __expf(sacc[t][0] - mnA); sacc[t][0] = p0; rsA += p0;
                float p1 = __expf(sacc[t][1] - mnA); sacc[t][1] = p1; rsA += p1;
                float p2 = __expf(sacc[t][2] - mnB); sacc[t][2] = p2; rsB += p2;
                float p3 = __expf(sacc[t][3] - mnB); sacc[t][3] = p3; rsB += p3;
            }
            rsA += __shfl_xor_sync(0xffffffffu, rsA, 1);
            rsA += __shfl_xor_sync(0xffffffffu, rsA, 2);
            rsB += __shfl_xor_sync(0xffffffffu, rsB, 1);
            rsB += __shfl_xor_sync(0xffffffffu, rsB, 2);

            lA = lA * corrA + rsA;
            lB = lB * corrB + rsB;
            #pragma unroll
            for (int t = 0; t < 8; ++t) {
                oacc[t][0] *= corrA; oacc[t][1] *= corrA;
                oacc[t][2] *= corrB; oacc[t][3] *= corrB;
            }
            mA = mnA; mB = mnB;

            #pragma unroll
            for (int ks = 0; ks < 4; ++ks) {
                if (ks > skip_lim) continue;   // P == 0 for this kv-row group
                uint32_t pfh[4], pfl[4];
                {
                    float h00, l00, h01, l01, h10, l10, h11, l11;
                    bsplit(sacc[2 * ks][0], h00, l00); bsplit(sacc[2 * ks][1], h01, l01);
                    bsplit(sacc[2 * ks][2], h10, l10); bsplit(sacc[2 * ks][3], h11, l11);
                    pfh[0] = packbf(h00, h01); pfl[0] = packbf(l00, l01);
                    pfh[1] = packbf(h10, h11); pfl[1] = packbf(l10, l11);
                    bsplit(sacc[2 * ks + 1][0], h00, l00); bsplit(sacc[2 * ks + 1][1], h01, l01);
                    bsplit(sacc[2 * ks + 1][2], h10, l10); bsplit(sacc[2 * ks + 1][3], h11, l11);
                    pfh[2] = packbf(h00, h01); pfl[2] = packbf(l00, l01);
                    pfh[3] = packbf(h10, h11); pfl[3] = packbf(l10, l11);
                }
                #pragma unroll
                for (int ep = 0; ep < 4; ++ep) {
                    uint32_t row = ks * 16 + vb_row;
                    uint32_t eo  = ep * 16 + vb_eoff;
                    uint32_t v0, v1, v2, v3, w0, w1, w2, w3;
                    LDSM_X4_T(v0, v1, v2, v3, Vh_b + row * 144 + eo * 2);
                    LDSM_X4_T(w0, w1, w2, w3, Vl_b + row * 144 + eo * 2);
                    mma16816(oacc[2 * ep],     pfh[0], pfh[1], pfh[2], pfh[3], v0, v1);
                    mma16816(oacc[2 * ep],     pfh[0], pfh[1], pfh[2], pfh[3], w0, w1);
                    mma16816(oacc[2 * ep],     pfl[0], pfl[1], pfl[2], pfl[3], v0, v1);
                    mma16816(oacc[2 * ep + 1], pfh[0], pfh[1], pfh[2], pfh[3], v2, v3);
                    mma16816(oacc[2 * ep + 1], pfh[0], pfh[1], pfh[2], pfh[3], w2, w3);
                    mma16816(oacc[2 * ep + 1], pfl[0], pfl[1], pfl[2], pfl[3], v2, v3);
                }
            }
        }

        const float invA = 1.0f / lA;
        const float invB = 1.0f / lB;
        const int b = bh >> 4, h = bh & 15;
        const int e0 = 2 * (lane & 3);
        size_t baseA = ((size_t)b * S_ + rA_g) * D_ + h * DH_;
        size_t baseB = ((size_t)b * S_ + rA_g + 8) * D_ + h * DH_;
        #pragma unroll
        for (int t = 0; t < 8; ++t) {
            int e = 8 * t + e0;
            float a0 = oacc[t][0] * invA, a1 = oacc[t][1] * invA;
            float b0v = oacc[t][2] * invB, b1v = oacc[t][3] * invB;
            float h0, l0, h1, l1;
            bsplit(a0, h0, l0); bsplit(a1, h1, l1);
            *(uint32_t*)(g_ch + baseA + e) = packbf(h0, h1);
            *(uint32_t*)(g_cl + baseA + e) = packbf(l0, l1);
            bsplit(b0v, h0, l0); bsplit(b1v, h1, l1);
            *(uint32_t*)(g_ch + baseB + e) = packbf(h0, h1);
            *(uint32_t*)(g_cl + baseB + e) = packbf(l0, l1);
        }
        __syncthreads();
    }
}

// ============================================================
extern "C" void kernel_launch(void* const* d_in, const int* in_sizes, int n_in,
                              void* d_out, int out_size)
{
    const float* x  = (const float*)d_in[0];
    const float* Wq = (const float*)d_in[1];
    const float* Wk = (const float*)d_in[2];
    const float* Wv = (const float*)d_in[3];
    const float* Wo = (const float*)d_in[4];
    const float* bo = (const float*)d_in[5];
    float* out = (float*)d_out;

    cudaFuncSetAttribute(qkv_mma_kernel, cudaFuncAttributeMaxDynamicSharedMemorySize, GEMM_SMEM);
    cudaFuncSetAttribute(out_proj_mma_kernel, cudaFuncAttributeMaxDynamicSharedMemorySize, GEMM_SMEM);
    cudaFuncSetAttribute(attn_mma_kernel, cudaFuncAttributeMaxDynamicSharedMemorySize, ATTN_SMEM);

    conv_all_kernel<<<9216, 256>>>(x, Wq, Wk, Wv, Wo);
    qkv_mma_kernel<<<PERSIST_CTAS, 256, GEMM_SMEM>>>();
    attn_mma_kernel<<<PERSIST_CTAS, 256, ATTN_SMEM>>>();
    out_proj_mma_kernel<<<PERSIST_CTAS, 256, GEMM_SMEM>>>(bo, out);
}

// round 16
// speedup vs baseline: 1.0284x; 1.0284x over previous
#include <cuda_runtime.h>
#include <cuda_bf16.h>
#include <cstdint>

#define B_ 4
#define S_ 2048
#define D_ 1024
#define H_ 16
#define DH_ 64
#define MROWS (B_ * S_)
#define QKV_ELEMS (B_ * H_ * S_ * DH_)   // 8388608
#define C_ELEMS   (B_ * S_ * D_)         // 8388608

// -------- bf16 hi/lo scratch (no allocation) --------
__device__ __nv_bfloat16 g_xh[C_ELEMS],  g_xl[C_ELEMS];
__device__ __nv_bfloat16 g_wt_h[3 * H_ * DH_ * D_], g_wt_l[3 * H_ * DH_ * D_];
__device__ __nv_bfloat16 g_wo_h[D_ * D_], g_wo_l[D_ * D_];
__device__ __nv_bfloat16 g_qh[QKV_ELEMS], g_ql[QKV_ELEMS];
__device__ __nv_bfloat16 g_kh[QKV_ELEMS], g_kl[QKV_ELEMS];
__device__ __nv_bfloat16 g_vh[QKV_ELEMS], g_vl[QKV_ELEMS];
__device__ __nv_bfloat16 g_ch[C_ELEMS],  g_cl[C_ELEMS];

// work-steal counters: [0]=qkv, [1]=attn, [2]=out_proj
__device__ unsigned int g_ctrs[3];

#define PERSIST_CTAS 304

// ================= helpers =================
__device__ __forceinline__ uint32_t smem_u32(const void* p) {
    uint32_t a;
    asm("{ .reg .u64 t; cvta.to.shared.u64 t, %1; cvt.u32.u64 %0, t; }" : "=r"(a) : "l"(p));
    return a;
}
__device__ __forceinline__ void bsplit(float v, float& h, float& l) {
    __nv_bfloat16 bh = __float2bfloat16(v);
    h = __bfloat162float(bh);
    l = v - h;
}
__device__ __forceinline__ uint32_t packbf(float lo_elem, float hi_elem) {
    uint32_t r;
    asm("cvt.rn.bf16x2.f32 %0, %1, %2;" : "=r"(r) : "f"(hi_elem), "f"(lo_elem));
    return r;
}
#define LDSM_X4(r0, r1, r2, r3, addr) \
    asm volatile("ldmatrix.sync.aligned.m8n8.x4.shared.b16 {%0,%1,%2,%3}, [%4];" \
        : "=r"(r0), "=r"(r1), "=r"(r2), "=r"(r3) : "r"(addr))
#define LDSM_X4_T(r0, r1, r2, r3, addr) \
    asm volatile("ldmatrix.sync.aligned.m8n8.x4.trans.shared.b16 {%0,%1,%2,%3}, [%4];" \
        : "=r"(r0), "=r"(r1), "=r"(r2), "=r"(r3) : "r"(addr))
#define CP_A16(sa, gp) asm volatile("cp.async.ca.shared.global [%0], [%1], 16;" :: "r"(sa), "l"(gp))
#define CP_COMMIT()    asm volatile("cp.async.commit_group;" ::: "memory")
#define CP_WAIT(n)     asm volatile("cp.async.wait_group %0;" :: "n"(n) : "memory")

__device__ __forceinline__ void mma16816(float* c,
    uint32_t a0, uint32_t a1, uint32_t a2, uint32_t a3, uint32_t b0, uint32_t b1)
{
    asm volatile(
        "mma.sync.aligned.m16n8k16.row.col.f32.bf16.bf16.f32 "
        "{%0,%1,%2,%3}, {%4,%5,%6,%7}, {%8,%9}, {%0,%1,%2,%3};"
        : "+f"(c[0]), "+f"(c[1]), "+f"(c[2]), "+f"(c[3])
        : "r"(a0), "r"(a1), "r"(a2), "r"(a3), "r"(b0), "r"(b1));
}

// ============================================================
// Fused preconversion kernel (x + W + Wo, one launch).
// x-part: MLP=4 (4 independent float4 per thread).
// Blocks [0,2048): conv_x; [2048,2816): conv_w; [2816,3072): conv_wo.
// ============================================================
__global__ __launch_bounds__(256) void conv_all_kernel(
    const float* __restrict__ x,
    const float* __restrict__ Wq, const float* __restrict__ Wk,
    const float* __restrict__ Wv, const float* __restrict__ Wo)
{
    __shared__ float ts[64][65];
    const int blk = blockIdx.x;
    const int tid = threadIdx.x;

    if (blk < 2048) {
        if (blk == 0 && tid < 3) g_ctrs[tid] = 0u;
        // 4 independent float4 loads per thread (MLP=4)
        float4 v[4];
        size_t base = (size_t)blk * 1024 + tid;
        #pragma unroll
        for (int i = 0; i < 4; ++i)
            v[i] = *(const float4*)(x + 4 * (base + (size_t)i * 256));
        #pragma unroll
        for (int i = 0; i < 4; ++i) {
            float hx, lx, hy, ly, hz, lz, hw, lw;
            bsplit(v[i].x, hx, lx); bsplit(v[i].y, hy, ly);
            bsplit(v[i].z, hz, lz); bsplit(v[i].w, hw, lw);
            uint2 wh, wl;
            wh.x = packbf(hx, hy); wh.y = packbf(hz, hw);
            wl.x = packbf(lx, ly); wl.y = packbf(lz, lw);
            size_t off = 4 * (base + (size_t)i * 256);
            *(uint2*)(g_xh + off) = wh;
            *(uint2*)(g_xl + off) = wl;
        }
        return;
    }

    if (blk < 2816) {
        const int q = blk - 2048;
        const int d0 = (q & 15) * 64;
        const int h  = (q >> 4) & 15;
        const int z  = q >> 8;
        const float* W = (z == 0) ? Wq : ((z == 1) ? Wk : Wv);
        const float* src = W + (size_t)h * D_ * DH_;

        #pragma unroll
        for (int i = 0; i < 4; ++i) {
            int idx = tid + i * 256;
            int rr = idx >> 4, cc = idx & 15;
            float4 v = *(const float4*)(src + (size_t)(d0 + rr) * DH_ + cc * 4);
            ts[rr][cc * 4 + 0] = v.x; ts[rr][cc * 4 + 1] = v.y;
            ts[rr][cc * 4 + 2] = v.z; ts[rr][cc * 4 + 3] = v.w;
        }
        __syncthreads();
        #pragma unroll
        for (int i = 0; i < 8; ++i) {
            int idx = tid + i * 256;
            int e = idx >> 5, w = idx & 31;
            float v0 = ts[2 * w][e], v1 = ts[2 * w + 1][e];
            float h0, l0, h1, l1;
            bsplit(v0, h0, l0); bsplit(v1, h1, l1);
            size_t off = ((size_t)(z * H_ + h) * DH_ + e) * D_ + d0 + 2 * w;
            *(uint32_t*)(g_wt_h + off) = packbf(h0, h1);
            *(uint32_t*)(g_wt_l + off) = packbf(l0, l1);
        }
        return;
    }

    {
        const int q = blk - 2816;
        const int d0 = (q & 15) * 64;
        const int f0 = (q >> 4) * 64;

        #pragma unroll
        for (int i = 0; i < 4; ++i) {
            int idx = tid + i * 256;
            int rr = idx >> 4, cc = idx & 15;
            float4 v = *(const float4*)(Wo + (size_t)(d0 + rr) * D_ + f0 + cc * 4);
            ts[rr][cc * 4 + 0] = v.x; ts[rr][cc * 4 + 1] = v.y;
            ts[rr][cc * 4 + 2] = v.z; ts[rr][cc * 4 + 3] = v.w;
        }
        __syncthreads();
        #pragma unroll
        for (int i = 0; i < 8; ++i) {
            int idx = tid + i * 256;
            int e = idx >> 5, w = idx & 31;
            float v0 = ts[2 * w][e], v1 = ts[2 * w + 1][e];
            float h0, l0, h1, l1;
            bsplit(v0, h0, l0); bsplit(v1, h1, l1);
            size_t off = (size_t)(f0 + e) * D_ + d0 + 2 * w;
            *(uint32_t*)(g_wo_h + off) = packbf(h0, h1);
            *(uint32_t*)(g_wo_l + off) = packbf(l0, l1);
        }
    }
}

// ============================================================
// GEMM machinery (R13 proven): 128x128 tile, BK=32, 8 warps,
// 2-stage cp.async, 2 CTAs/SM, persistent, ONE barrier/ktile,
// R12-style LDSM/MMA interleave.
// ============================================================
#define GEMM_STAGE 40960
#define GEMM_SMEM (2 * GEMM_STAGE)
#define NKT (D_ / 32)

__device__ __forceinline__ void gemm_load_stage(uint32_t sbase,
    const __nv_bfloat16* p0, const __nv_bfloat16* p1,
    const __nv_bfloat16* p2, const __nv_bfloat16* p3, int tid)
{
    const __nv_bfloat16* p[4] = {p0, p1, p2, p3};
    #pragma unroll
    for (int i = 0; i < 8; ++i) {
        int idx = tid + i * 256;
        int arr = idx >> 9;
        int c = idx & 511;
        int r = c >> 2, col = c & 3;
        const __nv_bfloat16* src = p[arr] + (size_t)r * D_ + col * 8;
        uint32_t sa = sbase + arr * 10240 + r * 80 + col * 16;
        CP_A16(sa, src);
    }
}

__device__ __forceinline__ void mma_phase(uint32_t sbase, float acc[4][4][4], int wid, int lane)
{
    const int warp_m = wid & 1;
    const int warp_n = wid >> 1;
    const uint32_t a_hi_b = sbase;
    const uint32_t a_lo_b = sbase + 10240;
    const uint32_t b_hi_b = sbase + 20480;
    const uint32_t b_lo_b = sbase + 30720;

    const int a_row = warp_m * 64 + (lane & 15);
    const int a_kh  = (lane >> 4) << 3;
    const int b_row = warp_n * 32 + (lane & 7) + ((lane >> 4) << 3);
    const int b_kh  = ((lane >> 3) & 1) << 3;

    #pragma unroll
    for (int ks = 0; ks < 2; ++ks) {
        const int koff = ks * 16;
        uint32_t bh[2][4], bl[2][4];
        #pragma unroll
        for (int jj = 0; jj < 2; ++jj) {
            LDSM_X4(bh[jj][0], bh[jj][1], bh[jj][2], bh[jj][3],
                    b_hi_b + ((b_row + jj * 16) * 40 + koff + b_kh) * 2);
            LDSM_X4(bl[jj][0], bl[jj][1], bl[jj][2], bl[jj][3],
                    b_lo_b + ((b_row + jj * 16) * 40 + koff + b_kh) * 2);
        }
        #pragma unroll
        for (int i = 0; i < 4; ++i) {
            uint32_t a0, a1, a2, a3;
            LDSM_X4(a0, a1, a2, a3,
                    a_hi_b + ((a_row + i * 16) * 40 + koff + a_kh) * 2);
            #pragma unroll
            for (int j = 0; j < 4; ++j) {
                int jj = j >> 1, s = (j & 1) * 2;
                mma16816(acc[i][j], a0, a1, a2, a3, bh[jj][s], bh[jj][s + 1]);
                mma16816(acc[i][j], a0, a1, a2, a3, bl[jj][s], bl[jj][s + 1]);
            }
            LDSM_X4(a0, a1, a2, a3,
                    a_lo_b + ((a_row + i * 16) * 40 + koff + a_kh) * 2);
            #pragma unroll
            for (int j = 0; j < 4; ++j) {
                int jj = j >> 1, s = (j & 1) * 2;
                mma16816(acc[i][j], a0, a1, a2, a3, bh[jj][s], bh[jj][s + 1]);
            }
        }
    }
}

#define GEMM_MAINLOOP(AH_, AL_, BH_, BL_)                                      \
    gemm_load_stage(smb, (AH_), (AL_), (BH_), (BL_), tid);                     \
    CP_COMMIT();                                                               \
    for (int kt = 0; kt < NKT; ++kt) {                                         \
        CP_WAIT(0);                                                            \
        __syncthreads();                                                       \
        if (kt + 1 < NKT) {                                                    \
            int k1 = (kt + 1) * 32;                                            \
            gemm_load_stage(smb + ((kt + 1) & 1) * GEMM_STAGE,                 \
                            (AH_) + k1, (AL_) + k1, (BH_) + k1, (BL_) + k1, tid); \
            CP_COMMIT();                                                       \
        }                                                                      \
        mma_phase(smb + (kt & 1) * GEMM_STAGE, acc, wid, lane);                \
    }

// ============================================================
// Kernel 1: QKV projection, persistent. tiles = 64*8*3 = 1536.
// ============================================================
#define QKV_TILES 1536

__global__ __launch_bounds__(256, 2) void qkv_mma_kernel()
{
    extern __shared__ char sm[];
    __shared__ int s_idx;
    const uint32_t smb = smem_u32(sm);
    const int tid = threadIdx.x;
    const int wid = tid >> 5;
    const int lane = tid & 31;

    for (;;) {
        if (tid == 0) s_idx = (int)atomicAdd(&g_ctrs[0], 1u);
        __syncthreads();
        const int idx = s_idx;
        if (idx >= QKV_TILES) return;

        const int m0 = (idx & 63) * 128;
        const int hp = (idx >> 6) & 7;
        const int z  = idx >> 9;

        __nv_bfloat16* outh = (z == 0) ? g_qh : ((z == 1) ? g_kh : g_vh);
        __nv_bfloat16* outl = (z == 0) ? g_ql : ((z == 1) ? g_kl : g_vl);
        const float scale = (z == 0) ? 0.125f : 1.0f;

        const __nv_bfloat16* ah = g_xh + (size_t)m0 * D_;
        const __nv_bfloat16* al = g_xl + (size_t)m0 * D_;
        const __nv_bfloat16* bh = g_wt_h + (size_t)(z * H_ + hp * 2) * DH_ * D_;
        const __nv_bfloat16* bl = g_wt_l + (size_t)(z * H_ + hp * 2) * DH_ * D_;

        float acc[4][4][4];
        #pragma unroll
        for (int i = 0; i < 4; ++i)
            #pragma unroll
            for (int j = 0; j < 4; ++j)
                #pragma unroll
                for (int q = 0; q < 4; ++q) acc[i][j][q] = 0.f;

        GEMM_MAINLOOP(ah, al, bh, bl)

        const int warp_m = wid & 1;
        const int warp_n = wid >> 1;
        #pragma unroll
        for (int i = 0; i < 4; ++i) {
            #pragma unroll
            for (int j = 0; j < 4; ++j) {
                int r0 = m0 + warp_m * 64 + i * 16 + (lane >> 2);
                int col = warp_n * 32 + j * 8 + (lane & 3) * 2;
                int hh = hp * 2 + (col >> 6);
                int ee = col & 63;
                #pragma unroll
                for (int half = 0; half < 2; ++half) {
                    int r = r0 + half * 8;
                    int b = r >> 11, s = r & 2047;
                    float v0 = acc[i][j][2 * half] * scale;
                    float v1 = acc[i][j][2 * half + 1] * scale;
                    float h0, l0, h1, l1;
                    bsplit(v0, h0, l0); bsplit(v1, h1, l1);
                    size_t off = ((size_t)(b * H_ + hh) * S_ + s) * DH_ + ee;
                    *(uint32_t*)(outh + off) = packbf(h0, h1);
                    *(uint32_t*)(outl + off) = packbf(l0, l1);
                }
            }
        }
        __syncthreads();
    }
}

// ============================================================
// Kernel 3: output projection, persistent. tiles = 64*8 = 512.
// ============================================================
#define OUT_TILES 512

__global__ __launch_bounds__(256, 2) void out_proj_mma_kernel(
    const float* __restrict__ bo, float* __restrict__ out)
{
    extern __shared__ char sm[];
    __shared__ int s_idx;
    const uint32_t smb = smem_u32(sm);
    const int tid = threadIdx.x;
    const int wid = tid >> 5;
    const int lane = tid & 31;

    for (;;) {
        if (tid == 0) s_idx = (int)atomicAdd(&g_ctrs[2], 1u);
        __syncthreads();
        const int idx = s_idx;
        if (idx >= OUT_TILES) return;

        const int m0 = (idx & 63) * 128;
        const int n0 = (idx >> 6) * 128;

        const __nv_bfloat16* ah = g_ch + (size_t)m0 * D_;
        const __nv_bfloat16* al = g_cl + (size_t)m0 * D_;
        const __nv_bfloat16* bh = g_wo_h + (size_t)n0 * D_;
        const __nv_bfloat16* bl = g_wo_l + (size_t)n0 * D_;

        float acc[4][4][4];
        #pragma unroll
        for (int i = 0; i < 4; ++i)
            #pragma unroll
            for (int j = 0; j < 4; ++j)
                #pragma unroll
                for (int q = 0; q < 4; ++q) acc[i][j][q] = 0.f;

        GEMM_MAINLOOP(ah, al, bh, bl)

        const int warp_m = wid & 1;
        const int warp_n = wid >> 1;
        #pragma unroll
        for (int i = 0; i < 4; ++i) {
            #pragma unroll
            for (int j = 0; j < 4; ++j) {
                int r0 = m0 + warp_m * 64 + i * 16 + (lane >> 2);
                int col = n0 + warp_n * 32 + j * 8 + (lane & 3) * 2;
                float b0 = bo[col], b1 = bo[col + 1];
                {
                    float2 v; v.x = acc[i][j][0] + b0; v.y = acc[i][j][1] + b1;
                    *(float2*)(out + (size_t)r0 * D_ + col) = v;
                }
                {
                    float2 v; v.x = acc[i][j][2] + b0; v.y = acc[i][j][3] + b1;
                    *(float2*)(out + (size_t)(r0 + 8) * D_ + col) = v;
                }
            }
        }
        __syncthreads();
    }
}

// ============================================================
// Kernel 2: causal flash attention, persistent + LPT (exact R13).
// ============================================================
#define KV_STAGE 36864
#define ATTN_SMEM (36864 + 2 * KV_STAGE)
#define ATTN_TILES 1024

__device__ __forceinline__ void attn_load_kv(uint32_t kvb,
    const __nv_bfloat16* kh, const __nv_bfloat16* kl,
    const __nv_bfloat16* vh, const __nv_bfloat16* vl, int tid)
{
    const __nv_bfloat16* p[4] = {kh, kl, vh, vl};
    #pragma unroll
    for (int i = 0; i < 8; ++i) {
        int idx = tid + i * 256;
        int arr = idx >> 9;
        int c = idx & 511;
        int r = c >> 3, c8 = c & 7;
        const __nv_bfloat16* src = p[arr] + (size_t)r * DH_ + c8 * 8;
        uint32_t sa = kvb + arr * 9216 + r * 144 + c8 * 16;
        CP_A16(sa, src);
    }
}

__global__ __launch_bounds__(256, 2) void attn_mma_kernel()
{
    extern __shared__ char sm[];
    __shared__ int s_idx;
    const uint32_t smb = smem_u32(sm);
    const int tid = threadIdx.x;
    const int wm = tid >> 5;
    const int lane = tid & 31;

    const uint32_t Qh_b = smb;
    const uint32_t Ql_b = smb + 18432;

    for (;;) {
        if (tid == 0) s_idx = (int)atomicAdd(&g_ctrs[1], 1u);
        __syncthreads();
        const int idx = s_idx;
        if (idx >= ATTN_TILES) return;

        const int qb = 15 - (idx >> 6);
        const int bh = idx & 63;
        const int kmax = 2 * qb + 2;

        const __nv_bfloat16* kh_g = g_kh + (size_t)bh * S_ * DH_;
        const __nv_bfloat16* kl_g = g_kl + (size_t)bh * S_ * DH_;
        const __nv_bfloat16* vh_g = g_vh + (size_t)bh * S_ * DH_;
        const __nv_bfloat16* vl_g = g_vl + (size_t)bh * S_ * DH_;

        attn_load_kv(smb + 36864, kh_g, kl_g, vh_g, vl_g, tid);
        CP_COMMIT();

        {
            const __nv_bfloat16* qh_g = g_qh + ((size_t)bh * S_ + qb * 128) * DH_;
            const __nv_bfloat16* ql_g = g_ql + ((size_t)bh * S_ + qb * 128) * DH_;
            #pragma unroll
            for (int i = 0; i < 4; ++i) {
                int ii = tid + i * 256;
                int r = ii >> 3, c8 = ii & 7;
                *(uint4*)(sm + (Qh_b - smb) + r * 144 + c8 * 16) =
                    *(const uint4*)(qh_g + (size_t)r * DH_ + c8 * 8);
                *(uint4*)(sm + (Ql_b - smb) + r * 144 + c8 * 16) =
                    *(const uint4*)(ql_g + (size_t)r * DH_ + c8 * 8);
            }
        }
        __syncthreads();

        uint32_t qh[4][4], ql[4][4];
        {
            const int ar = wm * 16 + (lane & 15);
            const int koff = (lane >> 4) << 3;
            #pragma unroll
            for (int ks = 0; ks < 4; ++ks) {
                LDSM_X4(qh[ks][0], qh[ks][1], qh[ks][2], qh[ks][3],
                        Qh_b + ar * 144 + (ks * 16 + koff) * 2);
                LDSM_X4(ql[ks][0], ql[ks][1], ql[ks][2], ql[ks][3],
                        Ql_b + ar * 144 + (ks * 16 + koff) * 2);
            }
        }

        float mA = -3.0e38f, mB = -3.0e38f, lA = 0.f, lB = 0.f;
        float oacc[8][4];
        #pragma unroll
        for (int t = 0; t < 8; ++t)
            #pragma unroll
            for (int q = 0; q < 4; ++q) oacc[t][q] = 0.f;

        const int kb_row  = (lane & 7) + ((lane >> 4) << 3);
        const int kb_koff = ((lane >> 3) & 1) << 3;
        const int vb_row  = (lane & 7) + (((lane >> 3) & 1) << 3);
        const int vb_eoff = (lane >> 4) << 3;

        const int rA_g = qb * 128 + wm * 16 + (lane >> 2);

        for (int kt = 0; kt < kmax; ++kt) {
            CP_WAIT(0);
            __syncthreads();
            if (kt + 1 < kmax) {
                size_t koff = (size_t)(kt + 1) * 64 * DH_;
                attn_load_kv(smb + 36864 + ((kt + 1) & 1) * KV_STAGE,
                             kh_g + koff, kl_g + koff, vh_g + koff, vl_g + koff, tid);
                CP_COMMIT();
            }

            const uint32_t kvb = smb + 36864 + (kt & 1) * KV_STAGE;
            const uint32_t Kh_b = kvb, Kl_b = kvb + 9216, Vh_b = kvb + 18432, Vl_b = kvb + 27648;

            float sacc[8][4];
            #pragma unroll
            for (int t = 0; t < 8; ++t)
                #pragma unroll
                for (int q = 0; q < 4; ++q) sacc[t][q] = 0.f;

            #pragma unroll
            for (int ks = 0; ks < 4; ++ks) {
                #pragma unroll
                for (int np = 0; np < 4; ++np) {
                    uint32_t row = np * 16 + kb_row;
                    uint32_t ko  = ks * 16 + kb_koff;
                    uint32_t b0, b1, b2, b3, c0, c1, c2, c3;
                    LDSM_X4(b0, b1, b2, b3, Kh_b + row * 144 + ko * 2);
                    LDSM_X4(c0, c1, c2, c3, Kl_b + row * 144 + ko * 2);
                    mma16816(sacc[2 * np],     qh[ks][0], qh[ks][1], qh[ks][2], qh[ks][3], b0, b1);
                    mma16816(sacc[2 * np],     qh[ks][0], qh[ks][1], qh[ks][2], qh[ks][3], c0, c1);
                    mma16816(sacc[2 * np],     ql[ks][0], ql[ks][1], ql[ks][2], ql[ks][3], b0, b1);
                    mma16816(sacc[2 * np + 1], qh[ks][0], qh[ks][1], qh[ks][2], qh[ks][3], b2, b3);
                    mma16816(sacc[2 * np + 1], qh[ks][0], qh[ks][1], qh[ks][2], qh[ks][3], c2, c3);
                    mma16816(sacc[2 * np + 1], ql[ks][0], ql[ks][1], ql[ks][2], ql[ks][3], b2, b3);
                }
            }

            if (kt >= 2 * qb) {
                const int c0g = kt * 64 + 2 * (lane & 3);
                #pragma unroll
                for (int t = 0; t < 8; ++t) {
                    int c = c0g + 8 * t;
                    if (c     > rA_g)     sacc[t][0] = -3.0e38f;
                    if (c + 1 > rA_g)     sacc[t][1] = -3.0e38f;
                    if (c     > rA_g + 8) sacc[t][2] = -3.0e38f;
                    if (c + 1 > rA_g + 8) sacc[t][3] = -3.0e38f;
                }
            }

            float mtA = -3.0e38f, mtB = -3.0e38f;
            #pragma unroll
            for (int t = 0; t < 8; ++t) {
                mtA = fmaxf(mtA, fmaxf(sacc[t][0], sacc[t][1]));
                mtB = fmaxf(mtB, fmaxf(sacc[t][2], sacc[t][3]));
            }
            mtA = fmaxf(mtA, __shfl_xor_sync(0xffffffffu, mtA, 1));
            mtA = fmaxf(mtA, __shfl_xor_sync(0xffffffffu, mtA, 2));
            mtB = fmaxf(mtB, __shfl_xor_sync(0xffffffffu, mtB, 1));
            mtB = fmaxf(mtB, __shfl_xor_sync(0xffffffffu, mtB, 2));

            float mnA = fmaxf(mA, mtA), mnB = fmaxf(mB, mtB);
            float corrA = __expf(mA - mnA), corrB = __expf(mB - mnB);

            float rsA = 0.f, rsB = 0.f;
            #pragma unroll
            for (int t = 0; t < 8; ++t) {
                float p0 = __expf(sacc[t][0] - mnA); sacc[t][0] = p0; rsA += p0;
                float p1 = __expf(sacc[t][1] - mnA); sacc[t][1] = p1; rsA += p1;
                float p2 = __expf(sacc[t][2] - mnB); sacc[t][2] = p2; rsB += p2;
                float p3 = __expf(sacc[t][3] - mnB); sacc[t][3] = p3; rsB += p3;
            }
            rsA += __shfl_xor_sync(0xffffffffu, rsA, 1);
            rsA += __shfl_xor_sync(0xffffffffu, rsA, 2);
            rsB += __shfl_xor_sync(0xffffffffu, rsB, 1);
            rsB += __shfl_xor_sync(0xffffffffu, rsB, 2);

            lA = lA * corrA + rsA;
            lB = lB * corrB + rsB;
            #pragma unroll
            for (int t = 0; t < 8; ++t) {
                oacc[t][0] *= corrA; oacc[t][1] *= corrA;
                oacc[t][2] *= corrB; oacc[t][3] *= corrB;
            }
            mA = mnA; mB = mnB;

            #pragma unroll
            for (int ks = 0; ks < 4; ++ks) {
                uint32_t pfh[4], pfl[4];
                {
                    float h00, l00, h01, l01, h10, l10, h11, l11;
                    bsplit(sacc[2 * ks][0], h00, l00); bsplit(sacc[2 * ks][1], h01, l01);
                    bsplit(sacc[2 * ks][2], h10, l10); bsplit(sacc[2 * ks][3], h11, l11);
                    pfh[0] = packbf(h00, h01); pfl[0] = packbf(l00, l01);
                    pfh[1] = packbf(h10, h11); pfl[1] = packbf(l10, l11);
                    bsplit(sacc[2 * ks + 1][0], h00, l00); bsplit(sacc[2 * ks + 1][1], h01, l01);
                    bsplit(sacc[2 * ks + 1][2], h10, l10); bsplit(sacc[2 * ks + 1][3], h11, l11);
                    pfh[2] = packbf(h00, h01); pfl[2] = packbf(l00, l01);
                    pfh[3] = packbf(h10, h11); pfl[3] = packbf(l10, l11);
                }
                #pragma unroll
                for (int ep = 0; ep < 4; ++ep) {
                    uint32_t row = ks * 16 + vb_row;
                    uint32_t eo  = ep * 16 + vb_eoff;
                    uint32_t v0, v1, v2, v3, w0, w1, w2, w3;
                    LDSM_X4_T(v0, v1, v2, v3, Vh_b + row * 144 + eo * 2);
                    LDSM_X4_T(w0, w1, w2, w3, Vl_b + row * 144 + eo * 2);
                    mma16816(oacc[2 * ep],     pfh[0], pfh[1], pfh[2], pfh[3], v0, v1);
                    mma16816(oacc[2 * ep],     pfh[0], pfh[1], pfh[2], pfh[3], w0, w1);
                    mma16816(oacc[2 * ep],     pfl[0], pfl[1], pfl[2], pfl[3], v0, v1);
                    mma16816(oacc[2 * ep + 1], pfh[0], pfh[1], pfh[2], pfh[3], v2, v3);
                    mma16816(oacc[2 * ep + 1], pfh[0], pfh[1], pfh[2], pfh[3], w2, w3);
                    mma16816(oacc[2 * ep + 1], pfl[0], pfl[1], pfl[2], pfl[3], v2, v3);
                }
            }
        }

        const float invA = 1.0f / lA;
        const float invB = 1.0f / lB;
        const int b = bh >> 4, h = bh & 15;
        const int e0 = 2 * (lane & 3);
        size_t baseA = ((size_t)b * S_ + rA_g) * D_ + h * DH_;
        size_t baseB = ((size_t)b * S_ + rA_g + 8) * D_ + h * DH_;
        #pragma unroll
        for (int t = 0; t < 8; ++t) {
            int e = 8 * t + e0;
            float a0 = oacc[t][0] * invA, a1 = oacc[t][1] * invA;
            float b0v = oacc[t][2] * invB, b1v = oacc[t][3] * invB;
            float h0, l0, h1, l1;
            bsplit(a0, h0, l0); bsplit(a1, h1, l1);
            *(uint32_t*)(g_ch + baseA + e) = packbf(h0, h1);
            *(uint32_t*)(g_cl + baseA + e) = packbf(l0, l1);
            bsplit(b0v, h0, l0); bsplit(b1v, h1, l1);
            *(uint32_t*)(g_ch + baseB + e) = packbf(h0, h1);
            *(uint32_t*)(g_cl + baseB + e) = packbf(l0, l1);
        }
        __syncthreads();
    }
}

// ============================================================
extern "C" void kernel_launch(void* const* d_in, const int* in_sizes, int n_in,
                              void* d_out, int out_size)
{
    const float* x  = (const float*)d_in[0];
    const float* Wq = (const float*)d_in[1];
    const float* Wk = (const float*)d_in[2];
    const float* Wv = (const float*)d_in[3];
    const float* Wo = (const float*)d_in[4];
    const float* bo = (const float*)d_in[5];
    float* out = (float*)d_out;

    cudaFuncSetAttribute(qkv_mma_kernel, cudaFuncAttributeMaxDynamicSharedMemorySize, GEMM_SMEM);
    cudaFuncSetAttribute(out_proj_mma_kernel, cudaFuncAttributeMaxDynamicSharedMemorySize, GEMM_SMEM);
    cudaFuncSetAttribute(attn_mma_kernel, cudaFuncAttributeMaxDynamicSharedMemorySize, ATTN_SMEM);

    conv_all_kernel<<<3072, 256>>>(x, Wq, Wk, Wv, Wo);
    qkv_mma_kernel<<<PERSIST_CTAS, 256, GEMM_SMEM>>>();
    attn_mma_kernel<<<PERSIST_CTAS, 256, ATTN_SMEM>>>();
    out_proj_mma_kernel<<<PERSIST_CTAS, 256, GEMM_SMEM>>>(bo, out);
}